// round 8
// baseline (speedup 1.0000x reference)
#include <cuda_runtime.h>
#include <cuda_fp16.h>

#define DIM    128
#define NPROJ  256
#define TPB    256
#define TOK_PER_CTA 128     // 8 warps x 16 tokens
#define TAU    0.03f        // 6.6 sigma of 1-term fp16 kp error
#define SCALE  ((float)(1.2533141373155003 / 256.0))   // sqrt(pi/2)/NPROJ

// S_hi (fp16) repacked for direct B-fragment LDG.128.
// uint4 index = ((nt*8 + j)*8 + g)*4 + tg  (nt: 16-proj tile, j: k-step, g: col, tg: k-pair)
//   v.x = hi(S[n_a][k0],  S[n_a][k0+1])   n_a = nt*16 + g,  k0 = tg*2 + 16*j
//   v.y = hi(S[n_a][k0+8],S[n_a][k0+9])
//   v.z = hi(S[n_b][k0],  S[n_b][k0+1])   n_b = n_a + 8
//   v.w = hi(S[n_b][k0+8],S[n_b][k0+9])
__device__ uint4 g_Sp[4096];   // 64 KB

__device__ __forceinline__ unsigned pack_h2(float x, float y) {
    __half2 h = __floats2half2_rn(x, y);
    return *reinterpret_cast<unsigned*>(&h);
}
__device__ __forceinline__ unsigned pack_h2_lo(float x, float y) {
    float rx = x - __half2float(__float2half_rn(x));
    float ry = y - __half2float(__float2half_rn(y));
    return pack_h2(rx, ry);
}

__global__ void prep_S(const float* __restrict__ S) {
    int idx = blockIdx.x * blockDim.x + threadIdx.x;   // 0..4095
    int tg = idx & 3, g = (idx >> 2) & 7, j = (idx >> 5) & 7, nt = idx >> 8;
    int n_a = nt * 16 + g, n_b = n_a + 8;
    int k0  = tg * 2 + 16 * j;
    const float* ra = S + (size_t)n_a * DIM;
    const float* rb = S + (size_t)n_b * DIM;
    uint4 v;
    v.x = pack_h2(ra[k0], ra[k0 + 1]);
    v.y = pack_h2(ra[k0 + 8], ra[k0 + 9]);
    v.z = pack_h2(rb[k0], rb[k0 + 1]);
    v.w = pack_h2(rb[k0 + 8], rb[k0 + 9]);
    g_Sp[idx] = v;
}

// mma.sync m16n8k16 fp16 -> f32 accumulate (baseline sm_80 ISA)
__device__ __forceinline__ void mma_f16(float* c, const unsigned* a,
                                        unsigned b0, unsigned b1) {
    asm volatile(
        "mma.sync.aligned.m16n8k16.row.col.f32.f16.f16.f32 "
        "{%0,%1,%2,%3}, {%4,%5,%6,%7}, {%8,%9}, {%0,%1,%2,%3};"
        : "+f"(c[0]), "+f"(c[1]), "+f"(c[2]), "+f"(c[3])
        : "r"(a[0]), "r"(a[1]), "r"(a[2]), "r"(a[3]), "r"(b0), "r"(b1));
}

// sign(kp)*qp with exact-fp32 recompute when |kp| is inside the fp16 error band.
__device__ __forceinline__ float term(float kp, float qp,
                                      const float* __restrict__ K,
                                      const float* __restrict__ S,
                                      int tok, int proj) {
    if (fabsf(kp) < TAU) {                 // rare (~2e-3): recompute exactly
        const float* kr = K + (size_t)tok * DIM;
        const float* sr = S + (size_t)proj * DIM;
        float s0 = 0.f, s1 = 0.f, s2 = 0.f, s3 = 0.f;
#pragma unroll 8
        for (int d = 0; d < DIM; d += 4) {
            s0 = fmaf(kr[d],     sr[d],     s0);
            s1 = fmaf(kr[d + 1], sr[d + 1], s1);
            s2 = fmaf(kr[d + 2], sr[d + 2], s2);
            s3 = fmaf(kr[d + 3], sr[d + 3], s3);
        }
        kp = (s0 + s1) + (s2 + s3);
        if (kp == 0.f) return 0.f;         // jnp.sign(0) == 0
    }
    return __uint_as_float(__float_as_uint(qp) ^
                           (__float_as_uint(kp) & 0x80000000u));
}

__global__ void __launch_bounds__(TPB, 1)
qjl_mma_kernel(const float* __restrict__ Q,
               const float* __restrict__ K,
               const float* __restrict__ S,
               float* __restrict__ out,
               int ntok)
{
    const int tid  = threadIdx.x;
    const int w    = tid >> 5;
    const int lane = tid & 31;
    const int g    = lane >> 2;            // row group / B column
    const int tg   = lane & 3;             // k-pair / C column pair

    const int base = blockIdx.x * TOK_PER_CTA + w * 16;
    const int tok0 = base + g, tok1 = base + g + 8;
    const int t0c  = tok0 < ntok ? tok0 : ntok - 1;
    const int t1c  = tok1 < ntok ? tok1 : ntok - 1;

    // ---- A fragments in registers: q_hi, q_lo, k_hi (fp16), K-dim = 128 ----
    unsigned qh[8][4], ql[8][4], kh[8][4];
    {
        const float* q0 = Q + (size_t)t0c * DIM;
        const float* q1 = Q + (size_t)t1c * DIM;
        const float* k0 = K + (size_t)t0c * DIM;
        const float* k1 = K + (size_t)t1c * DIM;
#pragma unroll
        for (int j = 0; j < 8; ++j) {
            const int c = tg * 2 + 16 * j;
            float2 v;
            v = *(const float2*)(q0 + c);     qh[j][0] = pack_h2(v.x, v.y); ql[j][0] = pack_h2_lo(v.x, v.y);
            v = *(const float2*)(q1 + c);     qh[j][1] = pack_h2(v.x, v.y); ql[j][1] = pack_h2_lo(v.x, v.y);
            v = *(const float2*)(q0 + c + 8); qh[j][2] = pack_h2(v.x, v.y); ql[j][2] = pack_h2_lo(v.x, v.y);
            v = *(const float2*)(q1 + c + 8); qh[j][3] = pack_h2(v.x, v.y); ql[j][3] = pack_h2_lo(v.x, v.y);
            v = *(const float2*)(k0 + c);     kh[j][0] = pack_h2(v.x, v.y);
            v = *(const float2*)(k1 + c);     kh[j][1] = pack_h2(v.x, v.y);
            v = *(const float2*)(k0 + c + 8); kh[j][2] = pack_h2(v.x, v.y);
            v = *(const float2*)(k1 + c + 8); kh[j][3] = pack_h2(v.x, v.y);
        }
    }

    float acc0 = 0.f, acc1 = 0.f;

    // ---- 16 projection tiles of n=16; per k-step: 3 MMAs x 2 n-halves ----
#pragma unroll 1
    for (int nt = 0; nt < 16; ++nt) {
        float cqa[4] = {0.f, 0.f, 0.f, 0.f};   // q_hi * S_hi   (n-half a)
        float cqb[4] = {0.f, 0.f, 0.f, 0.f};   // q_lo * S_hi
        float cka[4] = {0.f, 0.f, 0.f, 0.f};   // k_hi * S_hi
        float dqa[4] = {0.f, 0.f, 0.f, 0.f};   // (n-half b)
        float dqb[4] = {0.f, 0.f, 0.f, 0.f};
        float dka[4] = {0.f, 0.f, 0.f, 0.f};

        const uint4* bp = g_Sp + (size_t)nt * 256 + g * 4 + tg;
#pragma unroll
        for (int j = 0; j < 8; ++j) {
            uint4 b = bp[j * 32];
            mma_f16(cqa, qh[j], b.x, b.y);
            mma_f16(cqb, ql[j], b.x, b.y);
            mma_f16(cka, kh[j], b.x, b.y);
            mma_f16(dqa, qh[j], b.z, b.w);
            mma_f16(dqb, ql[j], b.z, b.w);
            mma_f16(dka, kh[j], b.z, b.w);
        }

        const int pa = nt * 16 + tg * 2;       // n-half a projection base
        const int pb = pa + 8;                 // n-half b
        acc0 += term(cka[0], cqa[0] + cqb[0], K, S, t0c, pa);
        acc0 += term(cka[1], cqa[1] + cqb[1], K, S, t0c, pa + 1);
        acc1 += term(cka[2], cqa[2] + cqb[2], K, S, t1c, pa);
        acc1 += term(cka[3], cqa[3] + cqb[3], K, S, t1c, pa + 1);
        acc0 += term(dka[0], dqa[0] + dqb[0], K, S, t0c, pb);
        acc0 += term(dka[1], dqa[1] + dqb[1], K, S, t0c, pb + 1);
        acc1 += term(dka[2], dqa[2] + dqb[2], K, S, t1c, pb);
        acc1 += term(dka[3], dqa[3] + dqb[3], K, S, t1c, pb + 1);
    }

    // ---- final reduction over the 4 lanes of each row group ----
    acc0 += __shfl_xor_sync(0xffffffffu, acc0, 1);
    acc0 += __shfl_xor_sync(0xffffffffu, acc0, 2);
    acc1 += __shfl_xor_sync(0xffffffffu, acc1, 1);
    acc1 += __shfl_xor_sync(0xffffffffu, acc1, 2);

    if (tg == 0) {
        if (tok0 < ntok) out[tok0] = SCALE * acc0;
        if (tok1 < ntok) out[tok1] = SCALE * acc1;
    }
}

extern "C" void kernel_launch(void* const* d_in, const int* in_sizes, int n_in,
                              void* d_out, int out_size) {
    // Identify S by element count (NPROJ*DIM = 32768); q precedes k among the rest.
    int s_idx = 2;
    for (int i = 0; i < n_in; ++i) if (in_sizes[i] == NPROJ * DIM) { s_idx = i; break; }
    int qk[2], wcnt = 0;
    for (int i = 0; i < n_in && wcnt < 2; ++i) if (i != s_idx) qk[wcnt++] = i;

    const float* Q = (const float*)d_in[qk[0]];  // query [B,H,SEQ,DIM] fp32
    const float* K = (const float*)d_in[qk[1]];  // key   [B,H,SEQ,DIM] fp32
    const float* S = (const float*)d_in[s_idx];  // S     [NPROJ,DIM]   fp32
    float* out = (float*)d_out;                  // [B,H,SEQ] fp32

    const int ntok   = in_sizes[qk[0]] / DIM;
    const int blocks = (ntok + TOK_PER_CTA - 1) / TOK_PER_CTA;

    prep_S<<<16, 256>>>(S);
    qjl_mma_kernel<<<blocks, TPB>>>(Q, K, S, out, ntok);
}

// round 9
// speedup vs baseline: 1.4505x; 1.4505x over previous
#include <cuda_runtime.h>
#include <cuda_fp16.h>

#define DIM    128
#define NPROJ  256
#define TPB    256
#define TOK_PER_CTA 128     // 8 warps x 16 tokens
#define TAU    0.025f       // ~9 sigma of 1-term fp16 kp error
#define SCALE  ((float)(1.2533141373155003 / 256.0))   // sqrt(pi/2)/NPROJ

// S repacked (fp16 hi/lo) for direct B-fragment LDG.128.
// uint4 index = ((n*8 + j)*4 + tg);  n = projection (B col), j = k-step, tg = k-pair
//   v.x = hi(S[n][k0],   S[n][k0+1])    k0 = tg*2 + 16*j
//   v.y = hi(S[n][k0+8], S[n][k0+9])
//   v.z = lo(S[n][k0],   S[n][k0+1])
//   v.w = lo(S[n][k0+8], S[n][k0+9])
__device__ uint4 g_Sp[NPROJ * 8 * 4];   // 128 KB

__device__ __forceinline__ unsigned pack_h2(float x, float y) {
    __half2 h = __floats2half2_rn(x, y);
    return *reinterpret_cast<unsigned*>(&h);
}
__device__ __forceinline__ unsigned pack_h2_lo(float x, float y) {
    float rx = x - __half2float(__float2half_rn(x));
    float ry = y - __half2float(__float2half_rn(y));
    return pack_h2(rx, ry);
}

__global__ void prep_S(const float* __restrict__ S) {
    int idx = blockIdx.x * blockDim.x + threadIdx.x;   // 0..8191 = (n*8 + j)*4 + tg
    int tg = idx & 3, j = (idx >> 2) & 7, n = idx >> 5;
    int d0 = tg * 2 + 16 * j;
    const float* row = S + (size_t)n * DIM;
    float x0 = row[d0], x1 = row[d0 + 1], y0 = row[d0 + 8], y1 = row[d0 + 9];
    uint4 v;
    v.x = pack_h2(x0, x1);     v.y = pack_h2(y0, y1);
    v.z = pack_h2_lo(x0, x1);  v.w = pack_h2_lo(y0, y1);
    g_Sp[idx] = v;
}

// mma.sync m16n8k16 fp16 -> f32 accumulate (baseline sm_80 ISA)
__device__ __forceinline__ void mma_f16(float* c, const unsigned* a,
                                        unsigned b0, unsigned b1) {
    asm volatile(
        "mma.sync.aligned.m16n8k16.row.col.f32.f16.f16.f32 "
        "{%0,%1,%2,%3}, {%4,%5,%6,%7}, {%8,%9}, {%0,%1,%2,%3};"
        : "+f"(c[0]), "+f"(c[1]), "+f"(c[2]), "+f"(c[3])
        : "r"(a[0]), "r"(a[1]), "r"(a[2]), "r"(a[3]), "r"(b0), "r"(b1));
}

__global__ void __launch_bounds__(TPB, 1)
qjl_mma_kernel(const float* __restrict__ Q,
               const float* __restrict__ K,
               const float* __restrict__ S,
               float* __restrict__ out,
               int ntok)
{
    const int tid  = threadIdx.x;
    const int w    = tid >> 5;
    const int lane = tid & 31;
    const int g    = lane >> 2;            // row group / C row
    const int tg   = lane & 3;             // k-pair / C column pair

    const int base = blockIdx.x * TOK_PER_CTA + w * 16;
    const int tok0 = base + g, tok1 = base + g + 8;
    const int t0c  = tok0 < ntok ? tok0 : ntok - 1;
    const int t1c  = tok1 < ntok ? tok1 : ntok - 1;

    // ---- A fragments in registers: q_hi, q_lo, k_hi (fp16), K-dim = 128 ----
    unsigned qh[8][4], ql[8][4], kh[8][4];
    {
        const float* q0 = Q + (size_t)t0c * DIM;
        const float* q1 = Q + (size_t)t1c * DIM;
        const float* k0 = K + (size_t)t0c * DIM;
        const float* k1 = K + (size_t)t1c * DIM;
#pragma unroll
        for (int j = 0; j < 8; ++j) {
            const int c = tg * 2 + 16 * j;
            float2 v;
            v = *(const float2*)(q0 + c);     qh[j][0] = pack_h2(v.x, v.y); ql[j][0] = pack_h2_lo(v.x, v.y);
            v = *(const float2*)(q1 + c);     qh[j][1] = pack_h2(v.x, v.y); ql[j][1] = pack_h2_lo(v.x, v.y);
            v = *(const float2*)(q0 + c + 8); qh[j][2] = pack_h2(v.x, v.y); ql[j][2] = pack_h2_lo(v.x, v.y);
            v = *(const float2*)(q1 + c + 8); qh[j][3] = pack_h2(v.x, v.y); ql[j][3] = pack_h2_lo(v.x, v.y);
            v = *(const float2*)(k0 + c);     kh[j][0] = pack_h2(v.x, v.y);
            v = *(const float2*)(k1 + c);     kh[j][1] = pack_h2(v.x, v.y);
            v = *(const float2*)(k0 + c + 8); kh[j][2] = pack_h2(v.x, v.y);
            v = *(const float2*)(k1 + c + 8); kh[j][3] = pack_h2(v.x, v.y);
        }
    }

    float acc0 = 0.f, acc1 = 0.f;

    // ---- 32 projection tiles of n=8; per k-step: 4 MMAs over 3 acc chains ----
#pragma unroll 1
    for (int nt = 0; nt < 32; ++nt) {
        float cqa[4] = {0.f, 0.f, 0.f, 0.f};   // q_hi * S_hi
        float cqb[4] = {0.f, 0.f, 0.f, 0.f};   // q_lo * S_hi + q_hi * S_lo
        float ck [4] = {0.f, 0.f, 0.f, 0.f};   // k_hi * S_hi   (sign only)

        const uint4* bq = g_Sp + ((size_t)(nt * 8 + g) * 8) * 4 + tg;
#pragma unroll
        for (int j = 0; j < 8; ++j) {
            uint4 b = bq[j * 4];
            mma_f16(cqa, qh[j], b.x, b.y);
            mma_f16(cqb, ql[j], b.x, b.y);
            mma_f16(cqb, qh[j], b.z, b.w);
            mma_f16(ck,  kh[j], b.x, b.y);
        }

        const int proj0 = nt * 8 + tg * 2;

        // ---- warp-cooperative exact-fp32 sign fix-up for marginal kp ----
#pragma unroll
        for (int p = 0; p < 4; ++p) {
            unsigned m = __ballot_sync(0xffffffffu, fabsf(ck[p]) < TAU);
            while (m) {                        // rare: ~7 events per warp total
                int src = __ffs(m) - 1; m &= m - 1;
                int stok  = __shfl_sync(0xffffffffu, (p & 2) ? t1c : t0c, src);
                int sproj = __shfl_sync(0xffffffffu, proj0 + (p & 1), src);
                float4 kv = *(const float4*)(K + (size_t)stok  * DIM + lane * 4);
                float4 sv = *(const float4*)(S + (size_t)sproj * DIM + lane * 4);
                float part = fmaf(kv.x, sv.x,
                             fmaf(kv.y, sv.y,
                             fmaf(kv.z, sv.z, kv.w * sv.w)));
#pragma unroll
                for (int o = 16; o; o >>= 1)
                    part += __shfl_xor_sync(0xffffffffu, part, o);
                if (lane == src) ck[p] = part;
            }
        }

        // ---- accumulate qp * sign(kp);  jnp.sign(0) == 0 ----
#pragma unroll
        for (int p = 0; p < 4; ++p) {
            float qp = cqa[p] + cqb[p];
            float t  = __uint_as_float(__float_as_uint(qp) ^
                                       (__float_as_uint(ck[p]) & 0x80000000u));
            if (ck[p] != 0.f) {
                if (p & 2) acc1 += t; else acc0 += t;
            }
        }
    }

    // ---- final reduction over the 4 lanes of each row group ----
    acc0 += __shfl_xor_sync(0xffffffffu, acc0, 1);
    acc0 += __shfl_xor_sync(0xffffffffu, acc0, 2);
    acc1 += __shfl_xor_sync(0xffffffffu, acc1, 1);
    acc1 += __shfl_xor_sync(0xffffffffu, acc1, 2);

    if (tg == 0) {
        if (tok0 < ntok) out[tok0] = SCALE * acc0;
        if (tok1 < ntok) out[tok1] = SCALE * acc1;
    }
}

extern "C" void kernel_launch(void* const* d_in, const int* in_sizes, int n_in,
                              void* d_out, int out_size) {
    // Identify S by element count (NPROJ*DIM = 32768); q precedes k among the rest.
    int s_idx = 2;
    for (int i = 0; i < n_in; ++i) if (in_sizes[i] == NPROJ * DIM) { s_idx = i; break; }
    int qk[2], wcnt = 0;
    for (int i = 0; i < n_in && wcnt < 2; ++i) if (i != s_idx) qk[wcnt++] = i;

    const float* Q = (const float*)d_in[qk[0]];  // query [B,H,SEQ,DIM] fp32
    const float* K = (const float*)d_in[qk[1]];  // key   [B,H,SEQ,DIM] fp32
    const float* S = (const float*)d_in[s_idx];  // S     [NPROJ,DIM]   fp32
    float* out = (float*)d_out;                  // [B,H,SEQ] fp32

    const int ntok   = in_sizes[qk[0]] / DIM;
    const int blocks = (ntok + TOK_PER_CTA - 1) / TOK_PER_CTA;

    prep_S<<<32, 256>>>(S);
    qjl_mma_kernel<<<blocks, TPB>>>(Q, K, S, out, ntok);
}